// round 8
// baseline (speedup 1.0000x reference)
#include <cuda_runtime.h>
#include <cuda_fp16.h>
#include <cstdint>

#define B_ 4
#define S_ 2048
#define D_ 1024
#define H_ 16
#define DK_ 64
#define M_ (B_ * S_)   // 8192

// Q pre-scale: (1/sqrt(64)) * log2(e)  -> scores in log2 domain
#define QSCALE 0.18033688011112042f

// Scratch (half precision)
__device__ __half g_Qh[(size_t)M_ * D_];
__device__ __half g_Kh[(size_t)M_ * D_];
__device__ __half g_Vh[(size_t)M_ * D_];
__device__ __half g_Ah[(size_t)M_ * D_];
__device__ __half g_WTh[4][(size_t)D_ * D_];   // transposed half weights [N,K]

// ---------------------------------------------------------------------------
// helpers
// ---------------------------------------------------------------------------
__device__ __forceinline__ uint32_t smem_u32(const void* p) {
    uint32_t a;
    asm("{ .reg .u64 t; cvta.to.shared.u64 t, %1; cvt.u32.u64 %0, t; }" : "=r"(a) : "l"(p));
    return a;
}
__device__ __forceinline__ uint32_t pack2(float a, float b) {
    __half2 h = __floats2half2_rn(a, b);
    return *(uint32_t*)&h;
}
__device__ __forceinline__ void ldm_x4(uint32_t r[4], uint32_t addr) {
    asm volatile("ldmatrix.sync.aligned.m8n8.x4.shared.b16 {%0,%1,%2,%3}, [%4];"
                 : "=r"(r[0]), "=r"(r[1]), "=r"(r[2]), "=r"(r[3]) : "r"(addr));
}
__device__ __forceinline__ void ldm_x4_t(uint32_t r[4], uint32_t addr) {
    asm volatile("ldmatrix.sync.aligned.m8n8.x4.trans.shared.b16 {%0,%1,%2,%3}, [%4];"
                 : "=r"(r[0]), "=r"(r[1]), "=r"(r[2]), "=r"(r[3]) : "r"(addr));
}
__device__ __forceinline__ void mma16816(float c[4], const uint32_t a[4],
                                         uint32_t b0, uint32_t b1) {
    asm volatile(
        "mma.sync.aligned.m16n8k16.row.col.f32.f16.f16.f32 "
        "{%0,%1,%2,%3}, {%4,%5,%6,%7}, {%8,%9}, {%0,%1,%2,%3};\n"
        : "+f"(c[0]), "+f"(c[1]), "+f"(c[2]), "+f"(c[3])
        : "r"(a[0]), "r"(a[1]), "r"(a[2]), "r"(a[3]), "r"(b0), "r"(b1));
}
#define CP_ASYNC16(dst, src) \
    asm volatile("cp.async.cg.shared.global [%0], [%1], 16;" :: "r"(dst), "l"(src))
#define CP_COMMIT()  asm volatile("cp.async.commit_group;" ::: "memory")
#define CP_WAIT0()   asm volatile("cp.async.wait_group 0;" ::: "memory")
#define CP_WAIT1()   asm volatile("cp.async.wait_group 1;" ::: "memory")

// ---------------------------------------------------------------------------
// Merged weight transpose + fp16 convert (all 4 weights, one launch)
// ---------------------------------------------------------------------------
struct WPtrs { const float* in[4]; __half* out[4]; };

__global__ __launch_bounds__(256)
void transposeWh4(WPtrs p)
{
    __shared__ float t[32][33];
    const float* in = p.in[blockIdx.z];
    __half* out = p.out[blockIdx.z];
    const int bx = blockIdx.x * 32, by = blockIdx.y * 32;
    const int tx = threadIdx.x & 31, ty = threadIdx.x >> 5;
    #pragma unroll
    for (int i = 0; i < 32; i += 8)
        t[ty + i][tx] = in[(size_t)(by + ty + i) * D_ + bx + tx];
    __syncthreads();
    #pragma unroll
    for (int i = 0; i < 32; i += 8)
        out[(size_t)(bx + ty + i) * D_ + by + tx] = __float2half_rn(t[tx][ty + i]);
}

// ---------------------------------------------------------------------------
// fp16 GEMM core: BM=128 BN=256 BK=32, 8 warps, warp tile 64x64,
// double-buffered dynamic SMEM, cp.async for half operands.
// ---------------------------------------------------------------------------
#define ASTR 40
#define NKT  (D_ / 32)
#define ABYTES (128 * ASTR * 2)   // 10240
#define BBYTES (256 * ASTR * 2)   // 20480
#define GDYN (2 * (ABYTES + BBYTES))   // 61440

template<bool AHALF, bool HEADOUT>
__device__ __forceinline__
void gemm_body(const void* __restrict__ Av, const __half* __restrict__ Wt,
               const float* __restrict__ bias, void* __restrict__ Cv,
               float scale, int m0, int n0)
{
    extern __shared__ __align__(16) __half dsm[];
    __half* As = dsm;                        // [2][128*ASTR]
    __half* Bs = dsm + 2 * 128 * ASTR;       // [2][256*ASTR]

    const int tid  = threadIdx.x;
    const int lane = tid & 31;
    const int warp = tid >> 5;
    const int wm = warp & 1;      // 2 warp rows (64 each)
    const int wn = warp >> 1;     // 4 warp cols (64 each)

    float acc[4][8][4];
    #pragma unroll
    for (int mt = 0; mt < 4; mt++)
        #pragma unroll
        for (int nt = 0; nt < 8; nt++)
            #pragma unroll
            for (int c = 0; c < 4; c++) acc[mt][nt][c] = 0.f;

    const int rowA = wm * 64 + ((lane >> 3) & 1) * 8 + (lane & 7);
    const int cbA  = lane >> 4;
    const int rowB = wn * 64 + (lane >> 4) * 8 + (lane & 7);
    const int cbB  = (lane >> 3) & 1;

    const uint32_t asB = smem_u32(As);
    const uint32_t bsB = smem_u32(Bs);

    float4 pa[4];

    #define ISSUE_B(k0, bufi)                                                   \
        _Pragma("unroll")                                                       \
        for (int q = 0; q < 4; q++) {                                           \
            const int idx = q * 256 + tid;                                      \
            const int r = idx >> 2, c8 = idx & 3;                               \
            CP_ASYNC16(bsB + (bufi) * BBYTES + (r * ASTR + 8 * c8) * 2,         \
                       Wt + (size_t)(n0 + r) * D_ + (k0) + 8 * c8);             \
        }
    #define ISSUE_A_ASYNC(k0, bufi)                                             \
        _Pragma("unroll")                                                       \
        for (int q = 0; q < 2; q++) {                                           \
            const int idx = q * 256 + tid;                                      \
            const int r = idx >> 2, c8 = idx & 3;                               \
            CP_ASYNC16(asB + (bufi) * ABYTES + (r * ASTR + 8 * c8) * 2,         \
                       (const __half*)Av + (size_t)(m0 + r) * D_ + (k0) + 8 * c8); \
        }
    #define LOAD_A(k0)                                                          \
        _Pragma("unroll")                                                       \
        for (int q = 0; q < 4; q++) {                                           \
            const int idx = q * 256 + tid;                                      \
            const int r = idx >> 3, c = idx & 7;                                \
            pa[q] = *(const float4*)((const float*)Av +                         \
                      (size_t)(m0 + r) * D_ + (k0) + 4 * c);                    \
        }
    #define STORE_A(bufi)                                                       \
        _Pragma("unroll")                                                       \
        for (int q = 0; q < 4; q++) {                                           \
            const int idx = q * 256 + tid;                                      \
            const int r = idx >> 3, c = idx & 7;                                \
            uint2 u = make_uint2(pack2(pa[q].x, pa[q].y),                       \
                                 pack2(pa[q].z, pa[q].w));                      \
            *(uint2*)&As[(bufi) * 128 * ASTR + r * ASTR + 4 * c] = u;           \
        }

    // prologue
    ISSUE_B(0, 0);
    if (AHALF) { ISSUE_A_ASYNC(0, 0); }
    else       { LOAD_A(0); STORE_A(0); }
    CP_COMMIT();
    CP_WAIT0();
    __syncthreads();

    for (int kt = 0; kt < NKT; kt++) {
        const int buf = kt & 1;
        if (kt + 1 < NKT) {
            const int kn = (kt + 1) * 32;
            ISSUE_B(kn, buf ^ 1);
            if (AHALF) { ISSUE_A_ASYNC(kn, buf ^ 1); }
            else       { LOAD_A(kn); }
            CP_COMMIT();
        }

        #pragma unroll
        for (int ks = 0; ks < 2; ks++) {
            uint32_t af[4][4];
            #pragma unroll
            for (int mt = 0; mt < 4; mt++)
                ldm_x4(af[mt], asB + buf * ABYTES +
                       2 * ((rowA + mt * 16) * ASTR + (2 * ks + cbA) * 8));
            #pragma unroll
            for (int g = 0; g < 4; g++) {
                uint32_t bf[4];
                ldm_x4(bf, bsB + buf * BBYTES +
                       2 * ((rowB + g * 16) * ASTR + (2 * ks + cbB) * 8));
                #pragma unroll
                for (int mt = 0; mt < 4; mt++) {
                    mma16816(acc[mt][2 * g],     af[mt], bf[0], bf[1]);
                    mma16816(acc[mt][2 * g + 1], af[mt], bf[2], bf[3]);
                }
            }
        }

        if (kt + 1 < NKT) {
            if (!AHALF) { STORE_A(buf ^ 1); }
            CP_WAIT0();
        }
        __syncthreads();
    }

    // epilogue
    const int fr = lane >> 2;
    const int fc = lane & 3;
    #pragma unroll
    for (int mt = 0; mt < 4; mt++) {
        #pragma unroll
        for (int nt = 0; nt < 8; nt++) {
            const int n = n0 + wn * 64 + nt * 8 + 2 * fc;
            const float b0 = bias[n], b1 = bias[n + 1];
            #pragma unroll
            for (int half_ : {0, 1}) {
                const int m = m0 + wm * 64 + mt * 16 + fr + half_ * 8;
                const float v0 = acc[mt][nt][2 * half_ + 0] + b0;
                const float v1 = acc[mt][nt][2 * half_ + 1] + b1;
                if (HEADOUT) {
                    const int b  = m >> 11;
                    const int s  = m & (S_ - 1);
                    const int h  = n >> 6;
                    const int dk = n & (DK_ - 1);
                    __half2 hv = __floats2half2_rn(v0 * scale, v1 * scale);
                    *(__half2*)((__half*)Cv +
                        ((size_t)((b << 4) + h) * S_ + s) * DK_ + dk) = hv;
                } else {
                    *(float2*)((float*)Cv + (size_t)m * D_ + n) = make_float2(v0, v1);
                }
            }
        }
    }
    #undef ISSUE_B
    #undef ISSUE_A_ASYNC
    #undef LOAD_A
    #undef STORE_A
}

// Fused Q/K/V projection: grid.x = 12 (3 matrices x 4 n-blocks)
__global__ __launch_bounds__(256)
void gemm_qkv(const float* __restrict__ q, const float* __restrict__ k,
              const float* __restrict__ v, const __half* __restrict__ WT,
              const float* __restrict__ bq, const float* __restrict__ bk,
              const float* __restrict__ bv,
              __half* __restrict__ Qs, __half* __restrict__ Ks, __half* __restrict__ Vs)
{
    const int mat = blockIdx.x >> 2;
    const int n0 = (blockIdx.x & 3) * 256;
    const int m0 = blockIdx.y * 128;
    const float* A = (mat == 0) ? q : (mat == 1) ? k : v;
    const float* bias = (mat == 0) ? bq : (mat == 1) ? bk : bv;
    __half* C = (mat == 0) ? Qs : (mat == 1) ? Ks : Vs;
    const __half* Wt = WT + (size_t)mat * D_ * D_;
    const float scale = (mat == 0) ? QSCALE : 1.0f;
    gemm_body<false, true>(A, Wt, bias, C, scale, m0, n0);
}

// Output projection
__global__ __launch_bounds__(256)
void gemm_out(const __half* __restrict__ A, const __half* __restrict__ Wt,
              const float* __restrict__ bias, float* __restrict__ C)
{
    gemm_body<true, false>(A, Wt, bias, C, 1.0f, blockIdx.y * 128, blockIdx.x * 256);
}

// ---------------------------------------------------------------------------
// fp16 flash attention: 4 warps x 32 q-rows (128 q/block), 64-key tiles,
// cp.async double-buffered K/V, f16x2 exp2, reg-resident P.
// Each K/V fragment load now feeds 2 row-groups (2x arithmetic intensity).
// ---------------------------------------------------------------------------
#define KSTR 72
#define KVBYTES (64 * KSTR * 2)   // 9216 bytes per tile buffer

__global__ __launch_bounds__(128, 2)
void attn_fp16(const __half* __restrict__ Qh, const __half* __restrict__ Kh,
               const __half* __restrict__ Vh, __half* __restrict__ O)
{
    __shared__ __align__(16) __half Ks[2][64 * KSTR];
    __shared__ __align__(16) __half Vs[2][64 * KSTR];

    const int tid  = threadIdx.x;
    const int lane = tid & 31;
    const int warp = tid >> 5;          // 0..3
    const int bh = blockIdx.y;
    const int b  = bh >> 4;
    const int h  = bh & (H_ - 1);
    const int q0 = blockIdx.x * 128;
    const int wrow = warp * 32;

    const int fr = lane >> 2;
    const int fc = lane & 3;

    // Q fragments: warp's 32 rows (2 groups of 16) x 64 dk
    uint32_t qa[2][4][4];
    {
        const __half* qb = Qh + ((size_t)bh * S_ + q0 + wrow) * DK_;
        #pragma unroll
        for (int grp = 0; grp < 2; grp++) {
            #pragma unroll
            for (int ks = 0; ks < 4; ks++) {
                const size_t r0 = (size_t)(grp * 16 + fr) * DK_;
                const size_t r1 = (size_t)(grp * 16 + fr + 8) * DK_;
                qa[grp][ks][0] = *(const uint32_t*)(qb + r0 + ks * 16 + 2 * fc);
                qa[grp][ks][1] = *(const uint32_t*)(qb + r1 + ks * 16 + 2 * fc);
                qa[grp][ks][2] = *(const uint32_t*)(qb + r0 + ks * 16 + 2 * fc + 8);
                qa[grp][ks][3] = *(const uint32_t*)(qb + r1 + ks * 16 + 2 * fc + 8);
            }
        }
    }

    float oacc[2][8][4];
    #pragma unroll
    for (int grp = 0; grp < 2; grp++)
        #pragma unroll
        for (int nt = 0; nt < 8; nt++)
            #pragma unroll
            for (int c = 0; c < 4; c++) oacc[grp][nt][c] = 0.f;

    float mv[2][2] = {{-1e30f, -1e30f}, {-1e30f, -1e30f}};
    float lv[2][2] = {{0.f, 0.f}, {0.f, 0.f}};

    const __half* kb = Kh + (size_t)bh * S_ * DK_;
    const __half* vb = Vh + (size_t)bh * S_ * DK_;

    const uint32_t ksB0 = smem_u32(&Ks[0][0]);
    const uint32_t vsB0 = smem_u32(&Vs[0][0]);

    const int rowK = (lane >> 4) * 8 + (lane & 7);
    const int cbK  = (lane >> 3) & 1;
    const int rowV = ((lane >> 3) & 1) * 8 + (lane & 7);
    const int cbV  = lane >> 4;

    // 1024 x 16B chunks (512 K + 512 V), 8 per thread (128 threads)
    #define ISSUE_TILE(t, bufi)                                                 \
        _Pragma("unroll")                                                       \
        for (int qq = 0; qq < 8; qq++) {                                        \
            const int c = qq * 128 + tid;                                       \
            const int kv = c >> 9;                                              \
            const int cc = c & 511;                                             \
            const int r = cc >> 3, c8 = cc & 7;                                 \
            const __half* src = (kv ? vb : kb) + (size_t)((t) * 64 + r) * DK_ + 8 * c8; \
            const uint32_t dst = (kv ? vsB0 : ksB0) + (bufi) * KVBYTES +        \
                                 (r * KSTR + 8 * c8) * 2;                       \
            CP_ASYNC16(dst, src);                                               \
        }

    ISSUE_TILE(0, 0); CP_COMMIT();

    for (int t = 0; t < S_ / 64; t++) {
        const int buf = t & 1;
        if (t + 1 < S_ / 64) { ISSUE_TILE(t + 1, buf ^ 1); CP_COMMIT(); CP_WAIT1(); }
        else                 { CP_WAIT0(); }
        __syncthreads();

        const uint32_t ksBase = ksB0 + buf * KVBYTES;
        const uint32_t vsBase = vsB0 + buf * KVBYTES;

        // S = Q K^T (log2-domain): each K fragment used by both row-groups
        float sacc[2][8][4];
        #pragma unroll
        for (int grp = 0; grp < 2; grp++)
            #pragma unroll
            for (int nt = 0; nt < 8; nt++)
                #pragma unroll
                for (int c = 0; c < 4; c++) sacc[grp][nt][c] = 0.f;

        #pragma unroll
        for (int ks = 0; ks < 4; ks++) {
            #pragma unroll
            for (int g = 0; g < 4; g++) {
                uint32_t bf[4];
                ldm_x4(bf, ksBase + 2 * ((g * 16 + rowK) * KSTR + (2 * ks + cbK) * 8));
                #pragma unroll
                for (int grp = 0; grp < 2; grp++) {
                    mma16816(sacc[grp][2 * g],     qa[grp][ks], bf[0], bf[1]);
                    mma16816(sacc[grp][2 * g + 1], qa[grp][ks], bf[2], bf[3]);
                }
            }
        }

        // online softmax per group (log2 domain)
        uint32_t p01[2][8], p23[2][8];
        #pragma unroll
        for (int grp = 0; grp < 2; grp++) {
            float rmax0 = -1e30f, rmax1 = -1e30f;
            #pragma unroll
            for (int nt = 0; nt < 8; nt++) {
                rmax0 = fmaxf(rmax0, fmaxf(sacc[grp][nt][0], sacc[grp][nt][1]));
                rmax1 = fmaxf(rmax1, fmaxf(sacc[grp][nt][2], sacc[grp][nt][3]));
            }
            #pragma unroll
            for (int off = 1; off < 4; off <<= 1) {
                rmax0 = fmaxf(rmax0, __shfl_xor_sync(0xffffffffu, rmax0, off));
                rmax1 = fmaxf(rmax1, __shfl_xor_sync(0xffffffffu, rmax1, off));
            }
            const float mn0 = fmaxf(mv[grp][0], rmax0);
            const float mn1 = fmaxf(mv[grp][1], rmax1);
            const float f0 = exp2f(mv[grp][0] - mn0);
            const float f1 = exp2f(mv[grp][1] - mn1);
            mv[grp][0] = mn0; mv[grp][1] = mn1;

            float rs0 = 0.f, rs1 = 0.f;
            #pragma unroll
            for (int nt = 0; nt < 8; nt++) {
                __half2 e0 = h2exp2(__floats2half2_rn(sacc[grp][nt][0] - mn0,
                                                      sacc[grp][nt][1] - mn0));
                __half2 e1 = h2exp2(__floats2half2_rn(sacc[grp][nt][2] - mn1,
                                                      sacc[grp][nt][3] - mn1));
                float2 g0 = __half22float2(e0); rs0 += g0.x + g0.y;
                float2 g1 = __half22float2(e1); rs1 += g1.x + g1.y;
                p01[grp][nt] = *(uint32_t*)&e0;
                p23[grp][nt] = *(uint32_t*)&e1;
            }
            #pragma unroll
            for (int off = 1; off < 4; off <<= 1) {
                rs0 += __shfl_xor_sync(0xffffffffu, rs0, off);
                rs1 += __shfl_xor_sync(0xffffffffu, rs1, off);
            }
            lv[grp][0] = lv[grp][0] * f0 + rs0;
            lv[grp][1] = lv[grp][1] * f1 + rs1;
            #pragma unroll
            for (int nt = 0; nt < 8; nt++) {
                oacc[grp][nt][0] *= f0; oacc[grp][nt][1] *= f0;
                oacc[grp][nt][2] *= f1; oacc[grp][nt][3] *= f1;
            }
        }

        // O += P V : each V fragment used by both row-groups
        #pragma unroll
        for (int ks = 0; ks < 4; ks++) {
            #pragma unroll
            for (int gp = 0; gp < 4; gp++) {
                uint32_t bf[4];
                ldm_x4_t(bf, vsBase + 2 * ((ks * 16 + rowV) * KSTR + (2 * gp + cbV) * 8));
                #pragma unroll
                for (int grp = 0; grp < 2; grp++) {
                    uint32_t pf[4];
                    pf[0] = p01[grp][2 * ks];
                    pf[1] = p23[grp][2 * ks];
                    pf[2] = p01[grp][2 * ks + 1];
                    pf[3] = p23[grp][2 * ks + 1];
                    mma16816(oacc[grp][2 * gp],     pf, bf[0], bf[1]);
                    mma16816(oacc[grp][2 * gp + 1], pf, bf[2], bf[3]);
                }
            }
        }
        __syncthreads();
    }

    // normalize + write half [B,S,D]
    #pragma unroll
    for (int grp = 0; grp < 2; grp++) {
        const float inv0 = 1.f / lv[grp][0];
        const float inv1 = 1.f / lv[grp][1];
        __half* ob = O + ((size_t)b * S_ + q0 + wrow + grp * 16) * D_ + h * DK_;
        #pragma unroll
        for (int nt = 0; nt < 8; nt++) {
            *(__half2*)(ob + (size_t)fr * D_ + nt * 8 + 2 * fc) =
                __floats2half2_rn(oacc[grp][nt][0] * inv0, oacc[grp][nt][1] * inv0);
            *(__half2*)(ob + (size_t)(fr + 8) * D_ + nt * 8 + 2 * fc) =
                __floats2half2_rn(oacc[grp][nt][2] * inv1, oacc[grp][nt][3] * inv1);
        }
    }
    #undef ISSUE_TILE
}

// ---------------------------------------------------------------------------
extern "C" void kernel_launch(void* const* d_in, const int* in_sizes, int n_in,
                              void* d_out, int out_size)
{
    const float* q  = (const float*)d_in[0];
    const float* k  = (const float*)d_in[1];
    const float* v  = (const float*)d_in[2];
    const float* wq = (const float*)d_in[3];
    const float* bq = (const float*)d_in[4];
    const float* wk = (const float*)d_in[5];
    const float* bk = (const float*)d_in[6];
    const float* wv = (const float*)d_in[7];
    const float* bv = (const float*)d_in[8];
    const float* wo = (const float*)d_in[9];
    const float* bo = (const float*)d_in[10];
    float* out = (float*)d_out;

    __half *Qs, *Ks, *Vs, *As, *WT;
    cudaGetSymbolAddress((void**)&Qs, g_Qh);
    cudaGetSymbolAddress((void**)&Ks, g_Kh);
    cudaGetSymbolAddress((void**)&Vs, g_Vh);
    cudaGetSymbolAddress((void**)&As, g_Ah);
    cudaGetSymbolAddress((void**)&WT, g_WTh);
    __half* WoT = WT + 3 * (size_t)D_ * D_;

    cudaFuncSetAttribute(gemm_qkv, cudaFuncAttributeMaxDynamicSharedMemorySize, GDYN);
    cudaFuncSetAttribute(gemm_out, cudaFuncAttributeMaxDynamicSharedMemorySize, GDYN);

    WPtrs wp;
    wp.in[0] = wq; wp.in[1] = wk; wp.in[2] = wv; wp.in[3] = wo;
    wp.out[0] = WT + 0 * (size_t)D_ * D_;
    wp.out[1] = WT + 1 * (size_t)D_ * D_;
    wp.out[2] = WT + 2 * (size_t)D_ * D_;
    wp.out[3] = WoT;

    transposeWh4<<<dim3(32, 32, 4), 256>>>(wp);

    gemm_qkv<<<dim3(12, M_ / 128), 256, GDYN>>>(q, k, v, WT, bq, bk, bv, Qs, Ks, Vs);

    attn_fp16<<<dim3(S_ / 128, B_ * H_), 128>>>(Qs, Ks, Vs, As);

    gemm_out<<<dim3(D_ / 256, M_ / 128), 256, GDYN>>>(As, WoT, bo, out);
}

// round 9
// speedup vs baseline: 1.4776x; 1.4776x over previous
#include <cuda_runtime.h>
#include <cuda_fp16.h>
#include <cstdint>

#define B_ 4
#define S_ 2048
#define D_ 1024
#define H_ 16
#define DK_ 64
#define M_ (B_ * S_)   // 8192

// Q pre-scale: (1/sqrt(64)) * log2(e)  -> scores in log2 domain
#define QSCALE 0.18033688011112042f

// Scratch (half precision)
__device__ __half g_Qh[(size_t)M_ * D_];
__device__ __half g_Kh[(size_t)M_ * D_];
__device__ __half g_Vh[(size_t)M_ * D_];
__device__ __half g_Ah[(size_t)M_ * D_];
__device__ __half g_WTh[4][(size_t)D_ * D_];   // transposed half weights [N,K]

// ---------------------------------------------------------------------------
// helpers
// ---------------------------------------------------------------------------
__device__ __forceinline__ uint32_t smem_u32(const void* p) {
    uint32_t a;
    asm("{ .reg .u64 t; cvta.to.shared.u64 t, %1; cvt.u32.u64 %0, t; }" : "=r"(a) : "l"(p));
    return a;
}
__device__ __forceinline__ uint32_t pack2(float a, float b) {
    __half2 h = __floats2half2_rn(a, b);
    return *(uint32_t*)&h;
}
__device__ __forceinline__ void ldm_x4(uint32_t r[4], uint32_t addr) {
    asm volatile("ldmatrix.sync.aligned.m8n8.x4.shared.b16 {%0,%1,%2,%3}, [%4];"
                 : "=r"(r[0]), "=r"(r[1]), "=r"(r[2]), "=r"(r[3]) : "r"(addr));
}
__device__ __forceinline__ void ldm_x4_t(uint32_t r[4], uint32_t addr) {
    asm volatile("ldmatrix.sync.aligned.m8n8.x4.trans.shared.b16 {%0,%1,%2,%3}, [%4];"
                 : "=r"(r[0]), "=r"(r[1]), "=r"(r[2]), "=r"(r[3]) : "r"(addr));
}
__device__ __forceinline__ void mma16816(float c[4], const uint32_t a[4],
                                         uint32_t b0, uint32_t b1) {
    asm volatile(
        "mma.sync.aligned.m16n8k16.row.col.f32.f16.f16.f32 "
        "{%0,%1,%2,%3}, {%4,%5,%6,%7}, {%8,%9}, {%0,%1,%2,%3};\n"
        : "+f"(c[0]), "+f"(c[1]), "+f"(c[2]), "+f"(c[3])
        : "r"(a[0]), "r"(a[1]), "r"(a[2]), "r"(a[3]), "r"(b0), "r"(b1));
}
#define CP_ASYNC16(dst, src) \
    asm volatile("cp.async.cg.shared.global [%0], [%1], 16;" :: "r"(dst), "l"(src))
#define CP_COMMIT()  asm volatile("cp.async.commit_group;" ::: "memory")
#define CP_WAIT0()   asm volatile("cp.async.wait_group 0;" ::: "memory")
#define CP_WAIT1()   asm volatile("cp.async.wait_group 1;" ::: "memory")

// ---------------------------------------------------------------------------
// Merged weight transpose + fp16 convert (all 4 weights, one launch)
// ---------------------------------------------------------------------------
struct WPtrs { const float* in[4]; __half* out[4]; };

__global__ __launch_bounds__(256)
void transposeWh4(WPtrs p)
{
    __shared__ float t[32][33];
    const float* in = p.in[blockIdx.z];
    __half* out = p.out[blockIdx.z];
    const int bx = blockIdx.x * 32, by = blockIdx.y * 32;
    const int tx = threadIdx.x & 31, ty = threadIdx.x >> 5;
    #pragma unroll
    for (int i = 0; i < 32; i += 8)
        t[ty + i][tx] = in[(size_t)(by + ty + i) * D_ + bx + tx];
    __syncthreads();
    #pragma unroll
    for (int i = 0; i < 32; i += 8)
        out[(size_t)(bx + ty + i) * D_ + by + tx] = __float2half_rn(t[tx][ty + i]);
}

// ---------------------------------------------------------------------------
// fp16 GEMM core: BM=128 BN=128 BK=32, 8 warps (warp tile 64x32),
// double-buffered static SMEM, cp.async for half operands (B always, A if half).
// This is the R6 (530us) shape + async loads; regs stay low -> 2 CTAs/SM.
// ---------------------------------------------------------------------------
#define ASTR 40
#define NKT  (D_ / 32)
#define TBYTES (128 * ASTR * 2)   // 10240 bytes per tile buffer

template<bool AHALF, bool HEADOUT>
__device__ __forceinline__
void gemm_body(const void* __restrict__ Av, const __half* __restrict__ Wt,
               const float* __restrict__ bias, void* __restrict__ Cv,
               float scale, int m0, int n0)
{
    __shared__ __align__(16) __half As[2][128 * ASTR];
    __shared__ __align__(16) __half Bs[2][128 * ASTR];

    const int tid  = threadIdx.x;
    const int lane = tid & 31;
    const int warp = tid >> 5;
    const int wm = warp & 1;      // 2 warp rows (64 each)
    const int wn = warp >> 1;     // 4 warp cols (32 each)

    float acc[4][4][4];
    #pragma unroll
    for (int mt = 0; mt < 4; mt++)
        #pragma unroll
        for (int nt = 0; nt < 4; nt++)
            #pragma unroll
            for (int c = 0; c < 4; c++) acc[mt][nt][c] = 0.f;

    const int rowA = wm * 64 + ((lane >> 3) & 1) * 8 + (lane & 7);
    const int cbA  = lane >> 4;
    const int rowB = wn * 32 + (lane >> 4) * 8 + (lane & 7);
    const int cbB  = (lane >> 3) & 1;

    const uint32_t asB = smem_u32(&As[0][0]);
    const uint32_t bsB = smem_u32(&Bs[0][0]);

    float4 pa[4];

    // B: 128 rows x 32 cols = 512 x 16B chunks, 2 per thread (cp.async)
    #define ISSUE_B(k0, bufi)                                                   \
        _Pragma("unroll")                                                       \
        for (int q = 0; q < 2; q++) {                                           \
            const int idx = q * 256 + tid;                                      \
            const int r = idx >> 2, c8 = idx & 3;                               \
            CP_ASYNC16(bsB + (bufi) * TBYTES + (r * ASTR + 8 * c8) * 2,         \
                       Wt + (size_t)(n0 + r) * D_ + (k0) + 8 * c8);             \
        }
    #define ISSUE_A_ASYNC(k0, bufi)                                             \
        _Pragma("unroll")                                                       \
        for (int q = 0; q < 2; q++) {                                           \
            const int idx = q * 256 + tid;                                      \
            const int r = idx >> 2, c8 = idx & 3;                               \
            CP_ASYNC16(asB + (bufi) * TBYTES + (r * ASTR + 8 * c8) * 2,         \
                       (const __half*)Av + (size_t)(m0 + r) * D_ + (k0) + 8 * c8); \
        }
    #define LOAD_A(k0)                                                          \
        _Pragma("unroll")                                                       \
        for (int q = 0; q < 4; q++) {                                           \
            const int idx = q * 256 + tid;                                      \
            const int r = idx >> 3, c = idx & 7;                                \
            pa[q] = *(const float4*)((const float*)Av +                         \
                      (size_t)(m0 + r) * D_ + (k0) + 4 * c);                    \
        }
    #define STORE_A(bufi)                                                       \
        _Pragma("unroll")                                                       \
        for (int q = 0; q < 4; q++) {                                           \
            const int idx = q * 256 + tid;                                      \
            const int r = idx >> 3, c = idx & 7;                                \
            uint2 u = make_uint2(pack2(pa[q].x, pa[q].y),                       \
                                 pack2(pa[q].z, pa[q].w));                      \
            *(uint2*)&As[bufi][r * ASTR + 4 * c] = u;                           \
        }

    // prologue
    ISSUE_B(0, 0);
    if (AHALF) { ISSUE_A_ASYNC(0, 0); }
    else       { LOAD_A(0); STORE_A(0); }
    CP_COMMIT();
    CP_WAIT0();
    __syncthreads();

    for (int kt = 0; kt < NKT; kt++) {
        const int buf = kt & 1;
        if (kt + 1 < NKT) {
            const int kn = (kt + 1) * 32;
            ISSUE_B(kn, buf ^ 1);
            if (AHALF) { ISSUE_A_ASYNC(kn, buf ^ 1); }
            else       { LOAD_A(kn); }
            CP_COMMIT();
        }

        #pragma unroll
        for (int ks = 0; ks < 2; ks++) {
            uint32_t af[4][4];
            #pragma unroll
            for (int mt = 0; mt < 4; mt++)
                ldm_x4(af[mt], asB + buf * TBYTES +
                       2 * ((rowA + mt * 16) * ASTR + (2 * ks + cbA) * 8));
            #pragma unroll
            for (int g = 0; g < 2; g++) {
                uint32_t bf[4];
                ldm_x4(bf, bsB + buf * TBYTES +
                       2 * ((rowB + g * 16) * ASTR + (2 * ks + cbB) * 8));
                #pragma unroll
                for (int mt = 0; mt < 4; mt++) {
                    mma16816(acc[mt][2 * g],     af[mt], bf[0], bf[1]);
                    mma16816(acc[mt][2 * g + 1], af[mt], bf[2], bf[3]);
                }
            }
        }

        if (kt + 1 < NKT) {
            if (!AHALF) { STORE_A(buf ^ 1); }
            CP_WAIT0();
        }
        __syncthreads();
    }

    // epilogue
    const int fr = lane >> 2;
    const int fc = lane & 3;
    #pragma unroll
    for (int mt = 0; mt < 4; mt++) {
        #pragma unroll
        for (int nt = 0; nt < 4; nt++) {
            const int n = n0 + wn * 32 + nt * 8 + 2 * fc;
            const float b0 = bias[n], b1 = bias[n + 1];
            #pragma unroll
            for (int half_ : {0, 1}) {
                const int m = m0 + wm * 64 + mt * 16 + fr + half_ * 8;
                const float v0 = acc[mt][nt][2 * half_ + 0] + b0;
                const float v1 = acc[mt][nt][2 * half_ + 1] + b1;
                if (HEADOUT) {
                    const int b  = m >> 11;
                    const int s  = m & (S_ - 1);
                    const int h  = n >> 6;
                    const int dk = n & (DK_ - 1);
                    __half2 hv = __floats2half2_rn(v0 * scale, v1 * scale);
                    *(__half2*)((__half*)Cv +
                        ((size_t)((b << 4) + h) * S_ + s) * DK_ + dk) = hv;
                } else {
                    *(float2*)((float*)Cv + (size_t)m * D_ + n) = make_float2(v0, v1);
                }
            }
        }
    }
    #undef ISSUE_B
    #undef ISSUE_A_ASYNC
    #undef LOAD_A
    #undef STORE_A
}

// Fused Q/K/V projection: grid.x = 24 (3 matrices x 8 n-blocks)
__global__ __launch_bounds__(256)
void gemm_qkv(const float* __restrict__ q, const float* __restrict__ k,
              const float* __restrict__ v, const __half* __restrict__ WT,
              const float* __restrict__ bq, const float* __restrict__ bk,
              const float* __restrict__ bv,
              __half* __restrict__ Qs, __half* __restrict__ Ks, __half* __restrict__ Vs)
{
    const int mat = blockIdx.x >> 3;
    const int n0 = (blockIdx.x & 7) * 128;
    const int m0 = blockIdx.y * 128;
    const float* A = (mat == 0) ? q : (mat == 1) ? k : v;
    const float* bias = (mat == 0) ? bq : (mat == 1) ? bk : bv;
    __half* C = (mat == 0) ? Qs : (mat == 1) ? Ks : Vs;
    const __half* Wt = WT + (size_t)mat * D_ * D_;
    const float scale = (mat == 0) ? QSCALE : 1.0f;
    gemm_body<false, true>(A, Wt, bias, C, scale, m0, n0);
}

// Output projection
__global__ __launch_bounds__(256)
void gemm_out(const __half* __restrict__ A, const __half* __restrict__ Wt,
              const float* __restrict__ bias, float* __restrict__ C)
{
    gemm_body<true, false>(A, Wt, bias, C, 1.0f, blockIdx.y * 128, blockIdx.x * 128);
}

// ---------------------------------------------------------------------------
// fp16 flash attention (R6 proven version): 8 warps x 16 q-rows (128 q/block),
// 64-key tiles, cp.async double-buffered K/V, f16x2 exp2, reg-resident P.
// ---------------------------------------------------------------------------
#define KSTR 72
#define KVBYTES (64 * KSTR * 2)   // 9216 bytes per tile buffer

__global__ __launch_bounds__(256, 2)
void attn_fp16(const __half* __restrict__ Qh, const __half* __restrict__ Kh,
               const __half* __restrict__ Vh, __half* __restrict__ O)
{
    __shared__ __align__(16) __half Ks[2][64 * KSTR];
    __shared__ __align__(16) __half Vs[2][64 * KSTR];

    const int tid  = threadIdx.x;
    const int lane = tid & 31;
    const int warp = tid >> 5;
    const int bh = blockIdx.y;
    const int b  = bh >> 4;
    const int h  = bh & (H_ - 1);
    const int q0 = blockIdx.x * 128;
    const int wrow = warp * 16;

    const int fr = lane >> 2;
    const int fc = lane & 3;

    // Q fragments: warp's 16 rows x 64 dk (Q pre-scaled by QSCALE)
    uint32_t qa[4][4];
    {
        const __half* qb = Qh + ((size_t)bh * S_ + q0 + wrow) * DK_;
        #pragma unroll
        for (int ks = 0; ks < 4; ks++) {
            qa[ks][0] = *(const uint32_t*)(qb + (size_t)fr * DK_ + ks * 16 + 2 * fc);
            qa[ks][1] = *(const uint32_t*)(qb + (size_t)(fr + 8) * DK_ + ks * 16 + 2 * fc);
            qa[ks][2] = *(const uint32_t*)(qb + (size_t)fr * DK_ + ks * 16 + 2 * fc + 8);
            qa[ks][3] = *(const uint32_t*)(qb + (size_t)(fr + 8) * DK_ + ks * 16 + 2 * fc + 8);
        }
    }

    float oacc[8][4];
    #pragma unroll
    for (int nt = 0; nt < 8; nt++)
        #pragma unroll
        for (int c = 0; c < 4; c++) oacc[nt][c] = 0.f;

    float m0v = -1e30f, m1v = -1e30f, l0 = 0.f, l1 = 0.f;

    const __half* kb = Kh + (size_t)bh * S_ * DK_;
    const __half* vb = Vh + (size_t)bh * S_ * DK_;

    const uint32_t ksB0 = smem_u32(&Ks[0][0]);
    const uint32_t vsB0 = smem_u32(&Vs[0][0]);

    const int rowK = (lane >> 4) * 8 + (lane & 7);
    const int cbK  = (lane >> 3) & 1;
    const int rowV = ((lane >> 3) & 1) * 8 + (lane & 7);
    const int cbV  = lane >> 4;

    // cp.async tile loader: 1024 x 16B chunks (512 K + 512 V), 4 per thread
    #define ISSUE_TILE(t, bufi)                                                 \
        _Pragma("unroll")                                                       \
        for (int qq = 0; qq < 4; qq++) {                                        \
            const int c = qq * 256 + tid;                                       \
            const int kv = c >> 9;                                              \
            const int cc = c & 511;                                             \
            const int r = cc >> 3, c8 = cc & 7;                                 \
            const __half* src = (kv ? vb : kb) + (size_t)((t) * 64 + r) * DK_ + 8 * c8; \
            const uint32_t dst = (kv ? vsB0 : ksB0) + (bufi) * KVBYTES +        \
                                 (r * KSTR + 8 * c8) * 2;                       \
            CP_ASYNC16(dst, src);                                               \
        }

    ISSUE_TILE(0, 0); CP_COMMIT();

    for (int t = 0; t < S_ / 64; t++) {
        const int buf = t & 1;
        if (t + 1 < S_ / 64) { ISSUE_TILE(t + 1, buf ^ 1); CP_COMMIT(); CP_WAIT1(); }
        else                 { CP_WAIT0(); }
        __syncthreads();

        const uint32_t ksBase = ksB0 + buf * KVBYTES;
        const uint32_t vsBase = vsB0 + buf * KVBYTES;

        // S = Q K^T (log2-domain scores)
        float sacc[8][4];
        #pragma unroll
        for (int nt = 0; nt < 8; nt++)
            #pragma unroll
            for (int c = 0; c < 4; c++) sacc[nt][c] = 0.f;

        #pragma unroll
        for (int ks = 0; ks < 4; ks++) {
            #pragma unroll
            for (int g = 0; g < 4; g++) {
                uint32_t bf[4];
                ldm_x4(bf, ksBase + 2 * ((g * 16 + rowK) * KSTR + (2 * ks + cbK) * 8));
                mma16816(sacc[2 * g],     qa[ks], bf[0], bf[1]);
                mma16816(sacc[2 * g + 1], qa[ks], bf[2], bf[3]);
            }
        }

        // online softmax in log2 domain
        float rmax0 = -1e30f, rmax1 = -1e30f;
        #pragma unroll
        for (int nt = 0; nt < 8; nt++) {
            rmax0 = fmaxf(rmax0, fmaxf(sacc[nt][0], sacc[nt][1]));
            rmax1 = fmaxf(rmax1, fmaxf(sacc[nt][2], sacc[nt][3]));
        }
        #pragma unroll
        for (int off = 1; off < 4; off <<= 1) {
            rmax0 = fmaxf(rmax0, __shfl_xor_sync(0xffffffffu, rmax0, off));
            rmax1 = fmaxf(rmax1, __shfl_xor_sync(0xffffffffu, rmax1, off));
        }
        const float mn0 = fmaxf(m0v, rmax0);
        const float mn1 = fmaxf(m1v, rmax1);
        const float f0 = exp2f(m0v - mn0);
        const float f1 = exp2f(m1v - mn1);
        m0v = mn0; m1v = mn1;

        // exp2 via f16x2 MUFU; P fragments built directly as half2 bits
        uint32_t p01[8], p23[8];
        float rs0 = 0.f, rs1 = 0.f;
        #pragma unroll
        for (int nt = 0; nt < 8; nt++) {
            __half2 e0 = h2exp2(__floats2half2_rn(sacc[nt][0] - m0v, sacc[nt][1] - m0v));
            __half2 e1 = h2exp2(__floats2half2_rn(sacc[nt][2] - m1v, sacc[nt][3] - m1v));
            float2 g0 = __half22float2(e0); rs0 += g0.x + g0.y;
            float2 g1 = __half22float2(e1); rs1 += g1.x + g1.y;
            p01[nt] = *(uint32_t*)&e0;
            p23[nt] = *(uint32_t*)&e1;
        }
        #pragma unroll
        for (int off = 1; off < 4; off <<= 1) {
            rs0 += __shfl_xor_sync(0xffffffffu, rs0, off);
            rs1 += __shfl_xor_sync(0xffffffffu, rs1, off);
        }
        l0 = l0 * f0 + rs0;
        l1 = l1 * f1 + rs1;
        #pragma unroll
        for (int nt = 0; nt < 8; nt++) {
            oacc[nt][0] *= f0; oacc[nt][1] *= f0;
            oacc[nt][2] *= f1; oacc[nt][3] *= f1;
        }

        // O += P V
        #pragma unroll
        for (int ks = 0; ks < 4; ks++) {
            uint32_t pf[4];
            pf[0] = p01[2 * ks];
            pf[1] = p23[2 * ks];
            pf[2] = p01[2 * ks + 1];
            pf[3] = p23[2 * ks + 1];
            #pragma unroll
            for (int gp = 0; gp < 4; gp++) {
                uint32_t bf[4];
                ldm_x4_t(bf, vsBase + 2 * ((ks * 16 + rowV) * KSTR + (2 * gp + cbV) * 8));
                mma16816(oacc[2 * gp],     pf, bf[0], bf[1]);
                mma16816(oacc[2 * gp + 1], pf, bf[2], bf[3]);
            }
        }
        __syncthreads();
    }

    // normalize + write half [B,S,D]
    const float inv0 = 1.f / l0;
    const float inv1 = 1.f / l1;
    __half* ob = O + ((size_t)b * S_ + q0 + wrow) * D_ + h * DK_;
    #pragma unroll
    for (int nt = 0; nt < 8; nt++) {
        *(__half2*)(ob + (size_t)fr * D_ + nt * 8 + 2 * fc) =
            __floats2half2_rn(oacc[nt][0] * inv0, oacc[nt][1] * inv0);
        *(__half2*)(ob + (size_t)(fr + 8) * D_ + nt * 8 + 2 * fc) =
            __floats2half2_rn(oacc[nt][2] * inv1, oacc[nt][3] * inv1);
    }
    #undef ISSUE_TILE
}

// ---------------------------------------------------------------------------
extern "C" void kernel_launch(void* const* d_in, const int* in_sizes, int n_in,
                              void* d_out, int out_size)
{
    const float* q  = (const float*)d_in[0];
    const float* k  = (const float*)d_in[1];
    const float* v  = (const float*)d_in[2];
    const float* wq = (const float*)d_in[3];
    const float* bq = (const float*)d_in[4];
    const float* wk = (const float*)d_in[5];
    const float* bk = (const float*)d_in[6];
    const float* wv = (const float*)d_in[7];
    const float* bv = (const float*)d_in[8];
    const float* wo = (const float*)d_in[9];
    const float* bo = (const float*)d_in[10];
    float* out = (float*)d_out;

    __half *Qs, *Ks, *Vs, *As, *WT;
    cudaGetSymbolAddress((void**)&Qs, g_Qh);
    cudaGetSymbolAddress((void**)&Ks, g_Kh);
    cudaGetSymbolAddress((void**)&Vs, g_Vh);
    cudaGetSymbolAddress((void**)&As, g_Ah);
    cudaGetSymbolAddress((void**)&WT, g_WTh);
    __half* WoT = WT + 3 * (size_t)D_ * D_;

    WPtrs wp;
    wp.in[0] = wq; wp.in[1] = wk; wp.in[2] = wv; wp.in[3] = wo;
    wp.out[0] = WT + 0 * (size_t)D_ * D_;
    wp.out[1] = WT + 1 * (size_t)D_ * D_;
    wp.out[2] = WT + 2 * (size_t)D_ * D_;
    wp.out[3] = WoT;

    transposeWh4<<<dim3(32, 32, 4), 256>>>(wp);

    gemm_qkv<<<dim3(24, M_ / 128), 256>>>(q, k, v, WT, bq, bk, bv, Qs, Ks, Vs);

    attn_fp16<<<dim3(S_ / 128, B_ * H_), 256>>>(Qs, Ks, Vs, As);

    gemm_out<<<dim3(D_ / 128, M_ / 128), 256>>>(As, WoT, bo, out);
}

// round 11
// speedup vs baseline: 1.5832x; 1.0715x over previous
#include <cuda_runtime.h>
#include <cuda_fp16.h>
#include <cstdint>

#define B_ 4
#define S_ 2048
#define D_ 1024
#define H_ 16
#define DK_ 64
#define M_ (B_ * S_)   // 8192

// Q pre-scale: (1/sqrt(64)) * log2(e)  -> scores in log2 domain
#define QSCALE 0.18033688011112042f

// Scratch (half precision)
__device__ __half g_Qh[(size_t)M_ * D_];
__device__ __half g_Kh[(size_t)M_ * D_];
__device__ __half g_Vh[(size_t)M_ * D_];
__device__ __half g_Ah[(size_t)M_ * D_];
__device__ __half g_Wh[4][(size_t)D_ * D_];   // fp16 weights, native [K,N] layout

// ---------------------------------------------------------------------------
// helpers
// ---------------------------------------------------------------------------
__device__ __forceinline__ uint32_t smem_u32(const void* p) {
    uint32_t a;
    asm("{ .reg .u64 t; cvta.to.shared.u64 t, %1; cvt.u32.u64 %0, t; }" : "=r"(a) : "l"(p));
    return a;
}
__device__ __forceinline__ uint32_t pack2(float a, float b) {
    __half2 h = __floats2half2_rn(a, b);
    return *(uint32_t*)&h;
}
__device__ __forceinline__ void ldm_x4(uint32_t r[4], uint32_t addr) {
    asm volatile("ldmatrix.sync.aligned.m8n8.x4.shared.b16 {%0,%1,%2,%3}, [%4];"
                 : "=r"(r[0]), "=r"(r[1]), "=r"(r[2]), "=r"(r[3]) : "r"(addr));
}
__device__ __forceinline__ void ldm_x4_t(uint32_t r[4], uint32_t addr) {
    asm volatile("ldmatrix.sync.aligned.m8n8.x4.trans.shared.b16 {%0,%1,%2,%3}, [%4];"
                 : "=r"(r[0]), "=r"(r[1]), "=r"(r[2]), "=r"(r[3]) : "r"(addr));
}
__device__ __forceinline__ void mma16816(float c[4], const uint32_t a[4],
                                         uint32_t b0, uint32_t b1) {
    asm volatile(
        "mma.sync.aligned.m16n8k16.row.col.f32.f16.f16.f32 "
        "{%0,%1,%2,%3}, {%4,%5,%6,%7}, {%8,%9}, {%0,%1,%2,%3};\n"
        : "+f"(c[0]), "+f"(c[1]), "+f"(c[2]), "+f"(c[3])
        : "r"(a[0]), "r"(a[1]), "r"(a[2]), "r"(a[3]), "r"(b0), "r"(b1));
}
#define CP_ASYNC16(dst, src) \
    asm volatile("cp.async.cg.shared.global [%0], [%1], 16;" :: "r"(dst), "l"(src))
#define CP_COMMIT()  asm volatile("cp.async.commit_group;" ::: "memory")
#define CP_WAIT0()   asm volatile("cp.async.wait_group 0;" ::: "memory")
#define CP_WAIT1()   asm volatile("cp.async.wait_group 1;" ::: "memory")

// ---------------------------------------------------------------------------
// Elementwise fp32 -> fp16 weight convert (no transpose; all 4 weights)
// ---------------------------------------------------------------------------
struct WPtrs { const float* in[4]; __half* out[4]; };

__global__ __launch_bounds__(256)
void convertWh4(WPtrs p)
{
    const float* in = p.in[blockIdx.z];
    __half* out = p.out[blockIdx.z];
    const size_t i = ((size_t)blockIdx.x * 256 + threadIdx.x) * 4;
    float4 v = *(const float4*)(in + i);
    uint2 u = make_uint2(pack2(v.x, v.y), pack2(v.z, v.w));
    *(uint2*)(out + i) = u;
}

// ---------------------------------------------------------------------------
// fp16 GEMM: C[M,N] = A[M,K] * W[K,N] + bias.  BM=128 BN=128 BK=32, 8 warps
// (warp tile 64x32). W kept K-major in SMEM; B-fragments via ldmatrix.trans
// (same addressing pattern as the attention V path). Pipeline: issue(kt+1),
// WAIT1 at top (prefetch overlaps full mma section), trailing sync.
// ---------------------------------------------------------------------------
#define ASTR 40
#define BSTR 136
#define ATILE (128 * ASTR * 2)   // 10240 B
#define BTILE (32 * BSTR * 2)    // 8704 B
#define NKT  (D_ / 32)

template<bool AHALF, bool HEADOUT>
__device__ __forceinline__
void gemm_body(const void* __restrict__ Av, const __half* __restrict__ Wh,
               const float* __restrict__ bias, void* __restrict__ Cv,
               float scale, int m0, int n0)
{
    __shared__ __align__(16) __half As[2][128 * ASTR];
    __shared__ __align__(16) __half Bs[2][32 * BSTR];

    const int tid  = threadIdx.x;
    const int lane = tid & 31;
    const int warp = tid >> 5;
    const int wm = warp & 1;      // 2 warp rows (64 each)
    const int wn = warp >> 1;     // 4 warp cols (32 each)

    float acc[4][4][4];
    #pragma unroll
    for (int mt = 0; mt < 4; mt++)
        #pragma unroll
        for (int nt = 0; nt < 4; nt++)
            #pragma unroll
            for (int c = 0; c < 4; c++) acc[mt][nt][c] = 0.f;

    const int rowA  = wm * 64 + ((lane >> 3) & 1) * 8 + (lane & 7);
    const int cbA   = lane >> 4;
    const int rowBt = ((lane >> 3) & 1) * 8 + (lane & 7);   // k within 16
    const int cbBt  = lane >> 4;                            // n-half (0/1)

    const uint32_t asB = smem_u32(&As[0][0]);
    const uint32_t bsB = smem_u32(&Bs[0][0]);

    float4 pa[4];

    // B tile: 32 k-rows x 128 n-cols = 512 x 16B chunks, 2 per thread
    #define ISSUE_B(k0, bufi)                                                   \
        _Pragma("unroll")                                                       \
        for (int q = 0; q < 2; q++) {                                           \
            const int idx = q * 256 + tid;                                      \
            const int r = idx >> 4, c8 = idx & 15;                              \
            CP_ASYNC16(bsB + (bufi) * BTILE + (r * BSTR + 8 * c8) * 2,          \
                       Wh + (size_t)((k0) + r) * D_ + n0 + 8 * c8);             \
        }
    #define ISSUE_A_ASYNC(k0, bufi)                                             \
        _Pragma("unroll")                                                       \
        for (int q = 0; q < 2; q++) {                                           \
            const int idx = q * 256 + tid;                                      \
            const int r = idx >> 2, c8 = idx & 3;                               \
            CP_ASYNC16(asB + (bufi) * ATILE + (r * ASTR + 8 * c8) * 2,          \
                       (const __half*)Av + (size_t)(m0 + r) * D_ + (k0) + 8 * c8); \
        }
    #define LOAD_A(k0)                                                          \
        _Pragma("unroll")                                                       \
        for (int q = 0; q < 4; q++) {                                           \
            const int idx = q * 256 + tid;                                      \
            const int r = idx >> 3, c = idx & 7;                                \
            pa[q] = *(const float4*)((const float*)Av +                         \
                      (size_t)(m0 + r) * D_ + (k0) + 4 * c);                    \
        }
    #define STORE_A(bufi)                                                       \
        _Pragma("unroll")                                                       \
        for (int q = 0; q < 4; q++) {                                           \
            const int idx = q * 256 + tid;                                      \
            const int r = idx >> 3, c = idx & 7;                                \
            uint2 u = make_uint2(pack2(pa[q].x, pa[q].y),                       \
                                 pack2(pa[q].z, pa[q].w));                      \
            *(uint2*)&As[bufi][r * ASTR + 4 * c] = u;                           \
        }

    // prologue: tile 0
    ISSUE_B(0, 0);
    if (AHALF) { ISSUE_A_ASYNC(0, 0); }
    else       { LOAD_A(0); STORE_A(0); }
    CP_COMMIT();

    for (int kt = 0; kt < NKT; kt++) {
        const int buf = kt & 1;
        if (kt + 1 < NKT) {
            const int kn = (kt + 1) * 32;
            ISSUE_B(kn, buf ^ 1);
            if (AHALF) { ISSUE_A_ASYNC(kn, buf ^ 1); }
            else       { LOAD_A(kn); }
            CP_COMMIT();
            CP_WAIT1();    // tile kt arrived; kt+1 still in flight
        } else {
            CP_WAIT0();
        }
        __syncthreads();

        #pragma unroll
        for (int ks = 0; ks < 2; ks++) {
            uint32_t af[4][4];
            #pragma unroll
            for (int mt = 0; mt < 4; mt++)
                ldm_x4(af[mt], asB + buf * ATILE +
                       2 * ((rowA + mt * 16) * ASTR + (2 * ks + cbA) * 8));
            #pragma unroll
            for (int g = 0; g < 2; g++) {
                uint32_t bf[4];
                // col = wn*32 + g*16 + cbBt*8  (FIX: only the half-selector is x8)
                ldm_x4_t(bf, bsB + buf * BTILE +
                         2 * ((ks * 16 + rowBt) * BSTR + wn * 32 + g * 16 + cbBt * 8));
                #pragma unroll
                for (int mt = 0; mt < 4; mt++) {
                    mma16816(acc[mt][2 * g],     af[mt], bf[0], bf[1]);
                    mma16816(acc[mt][2 * g + 1], af[mt], bf[2], bf[3]);
                }
            }
        }

        if (kt + 1 < NKT && !AHALF) { STORE_A(buf ^ 1); }
        __syncthreads();   // all warps done with tile kt before its buffer is refilled
    }

    // epilogue
    const int fr = lane >> 2;
    const int fc = lane & 3;
    #pragma unroll
    for (int mt = 0; mt < 4; mt++) {
        #pragma unroll
        for (int nt = 0; nt < 4; nt++) {
            const int n = n0 + wn * 32 + nt * 8 + 2 * fc;
            const float b0 = bias[n], b1 = bias[n + 1];
            #pragma unroll
            for (int half_ : {0, 1}) {
                const int m = m0 + wm * 64 + mt * 16 + fr + half_ * 8;
                const float v0 = acc[mt][nt][2 * half_ + 0] + b0;
                const float v1 = acc[mt][nt][2 * half_ + 1] + b1;
                if (HEADOUT) {
                    const int b  = m >> 11;
                    const int s  = m & (S_ - 1);
                    const int h  = n >> 6;
                    const int dk = n & (DK_ - 1);
                    __half2 hv = __floats2half2_rn(v0 * scale, v1 * scale);
                    *(__half2*)((__half*)Cv +
                        ((size_t)((b << 4) + h) * S_ + s) * DK_ + dk) = hv;
                } else {
                    *(float2*)((float*)Cv + (size_t)m * D_ + n) = make_float2(v0, v1);
                }
            }
        }
    }
    #undef ISSUE_B
    #undef ISSUE_A_ASYNC
    #undef LOAD_A
    #undef STORE_A
}

// Fused Q/K/V projection: grid.x = 24 (3 matrices x 8 n-blocks)
__global__ __launch_bounds__(256)
void gemm_qkv(const float* __restrict__ q, const float* __restrict__ k,
              const float* __restrict__ v, const __half* __restrict__ W4,
              const float* __restrict__ bq, const float* __restrict__ bk,
              const float* __restrict__ bv,
              __half* __restrict__ Qs, __half* __restrict__ Ks, __half* __restrict__ Vs)
{
    const int mat = blockIdx.x >> 3;
    const int n0 = (blockIdx.x & 7) * 128;
    const int m0 = blockIdx.y * 128;
    const float* A = (mat == 0) ? q : (mat == 1) ? k : v;
    const float* bias = (mat == 0) ? bq : (mat == 1) ? bk : bv;
    __half* C = (mat == 0) ? Qs : (mat == 1) ? Ks : Vs;
    const __half* Wh = W4 + (size_t)mat * D_ * D_;
    const float scale = (mat == 0) ? QSCALE : 1.0f;
    gemm_body<false, true>(A, Wh, bias, C, scale, m0, n0);
}

// Output projection
__global__ __launch_bounds__(256)
void gemm_out(const __half* __restrict__ A, const __half* __restrict__ Wh,
              const float* __restrict__ bias, float* __restrict__ C)
{
    gemm_body<true, false>(A, Wh, bias, C, 1.0f, blockIdx.y * 128, blockIdx.x * 128);
}

// ---------------------------------------------------------------------------
// fp16 flash attention (proven 530us version, unchanged): 8 warps x 16 q-rows,
// 64-key tiles, cp.async double-buffered K/V, f16x2 exp2, reg-resident P.
// ---------------------------------------------------------------------------
#define KSTR 72
#define KVBYTES (64 * KSTR * 2)   // 9216 bytes per tile buffer

__global__ __launch_bounds__(256, 2)
void attn_fp16(const __half* __restrict__ Qh, const __half* __restrict__ Kh,
               const __half* __restrict__ Vh, __half* __restrict__ O)
{
    __shared__ __align__(16) __half Ks[2][64 * KSTR];
    __shared__ __align__(16) __half Vs[2][64 * KSTR];

    const int tid  = threadIdx.x;
    const int lane = tid & 31;
    const int warp = tid >> 5;
    const int bh = blockIdx.y;
    const int b  = bh >> 4;
    const int h  = bh & (H_ - 1);
    const int q0 = blockIdx.x * 128;
    const int wrow = warp * 16;

    const int fr = lane >> 2;
    const int fc = lane & 3;

    uint32_t qa[4][4];
    {
        const __half* qb = Qh + ((size_t)bh * S_ + q0 + wrow) * DK_;
        #pragma unroll
        for (int ks = 0; ks < 4; ks++) {
            qa[ks][0] = *(const uint32_t*)(qb + (size_t)fr * DK_ + ks * 16 + 2 * fc);
            qa[ks][1] = *(const uint32_t*)(qb + (size_t)(fr + 8) * DK_ + ks * 16 + 2 * fc);
            qa[ks][2] = *(const uint32_t*)(qb + (size_t)fr * DK_ + ks * 16 + 2 * fc + 8);
            qa[ks][3] = *(const uint32_t*)(qb + (size_t)(fr + 8) * DK_ + ks * 16 + 2 * fc + 8);
        }
    }

    float oacc[8][4];
    #pragma unroll
    for (int nt = 0; nt < 8; nt++)
        #pragma unroll
        for (int c = 0; c < 4; c++) oacc[nt][c] = 0.f;

    float m0v = -1e30f, m1v = -1e30f, l0 = 0.f, l1 = 0.f;

    const __half* kb = Kh + (size_t)bh * S_ * DK_;
    const __half* vb = Vh + (size_t)bh * S_ * DK_;

    const uint32_t ksB0 = smem_u32(&Ks[0][0]);
    const uint32_t vsB0 = smem_u32(&Vs[0][0]);

    const int rowK = (lane >> 4) * 8 + (lane & 7);
    const int cbK  = (lane >> 3) & 1;
    const int rowV = ((lane >> 3) & 1) * 8 + (lane & 7);
    const int cbV  = lane >> 4;

    #define ISSUE_TILE(t, bufi)                                                 \
        _Pragma("unroll")                                                       \
        for (int qq = 0; qq < 4; qq++) {                                        \
            const int c = qq * 256 + tid;                                       \
            const int kv = c >> 9;                                              \
            const int cc = c & 511;                                             \
            const int r = cc >> 3, c8 = cc & 7;                                 \
            const __half* src = (kv ? vb : kb) + (size_t)((t) * 64 + r) * DK_ + 8 * c8; \
            const uint32_t dst = (kv ? vsB0 : ksB0) + (bufi) * KVBYTES +        \
                                 (r * KSTR + 8 * c8) * 2;                       \
            CP_ASYNC16(dst, src);                                               \
        }

    ISSUE_TILE(0, 0); CP_COMMIT();

    for (int t = 0; t < S_ / 64; t++) {
        const int buf = t & 1;
        if (t + 1 < S_ / 64) { ISSUE_TILE(t + 1, buf ^ 1); CP_COMMIT(); CP_WAIT1(); }
        else                 { CP_WAIT0(); }
        __syncthreads();

        const uint32_t ksBase = ksB0 + buf * KVBYTES;
        const uint32_t vsBase = vsB0 + buf * KVBYTES;

        float sacc[8][4];
        #pragma unroll
        for (int nt = 0; nt < 8; nt++)
            #pragma unroll
            for (int c = 0; c < 4; c++) sacc[nt][c] = 0.f;

        #pragma unroll
        for (int ks = 0; ks < 4; ks++) {
            #pragma unroll
            for (int g = 0; g < 4; g++) {
                uint32_t bf[4];
                ldm_x4(bf, ksBase + 2 * ((g * 16 + rowK) * KSTR + (2 * ks + cbK) * 8));
                mma16816(sacc[2 * g],     qa[ks], bf[0], bf[1]);
                mma16816(sacc[2 * g + 1], qa[ks], bf[2], bf[3]);
            }
        }

        float rmax0 = -1e30f, rmax1 = -1e30f;
        #pragma unroll
        for (int nt = 0; nt < 8; nt++) {
            rmax0 = fmaxf(rmax0, fmaxf(sacc[nt][0], sacc[nt][1]));
            rmax1 = fmaxf(rmax1, fmaxf(sacc[nt][2], sacc[nt][3]));
        }
        #pragma unroll
        for (int off = 1; off < 4; off <<= 1) {
            rmax0 = fmaxf(rmax0, __shfl_xor_sync(0xffffffffu, rmax0, off));
            rmax1 = fmaxf(rmax1, __shfl_xor_sync(0xffffffffu, rmax1, off));
        }
        const float mn0 = fmaxf(m0v, rmax0);
        const float mn1 = fmaxf(m1v, rmax1);
        const float f0 = exp2f(m0v - mn0);
        const float f1 = exp2f(m1v - mn1);
        m0v = mn0; m1v = mn1;

        uint32_t p01[8], p23[8];
        float rs0 = 0.f, rs1 = 0.f;
        #pragma unroll
        for (int nt = 0; nt < 8; nt++) {
            __half2 e0 = h2exp2(__floats2half2_rn(sacc[nt][0] - m0v, sacc[nt][1] - m0v));
            __half2 e1 = h2exp2(__floats2half2_rn(sacc[nt][2] - m1v, sacc[nt][3] - m1v));
            float2 g0 = __half22float2(e0); rs0 += g0.x + g0.y;
            float2 g1 = __half22float2(e1); rs1 += g1.x + g1.y;
            p01[nt] = *(uint32_t*)&e0;
            p23[nt] = *(uint32_t*)&e1;
        }
        #pragma unroll
        for (int off = 1; off < 4; off <<= 1) {
            rs0 += __shfl_xor_sync(0xffffffffu, rs0, off);
            rs1 += __shfl_xor_sync(0xffffffffu, rs1, off);
        }
        l0 = l0 * f0 + rs0;
        l1 = l1 * f1 + rs1;
        #pragma unroll
        for (int nt = 0; nt < 8; nt++) {
            oacc[nt][0] *= f0; oacc[nt][1] *= f0;
            oacc[nt][2] *= f1; oacc[nt][3] *= f1;
        }

        #pragma unroll
        for (int ks = 0; ks < 4; ks++) {
            uint32_t pf[4];
            pf[0] = p01[2 * ks];
            pf[1] = p23[2 * ks];
            pf[2] = p01[2 * ks + 1];
            pf[3] = p23[2 * ks + 1];
            #pragma unroll
            for (int gp = 0; gp < 4; gp++) {
                uint32_t bf[4];
                ldm_x4_t(bf, vsBase + 2 * ((ks * 16 + rowV) * KSTR + (2 * gp + cbV) * 8));
                mma16816(oacc[2 * gp],     pf, bf[0], bf[1]);
                mma16816(oacc[2 * gp + 1], pf, bf[2], bf[3]);
            }
        }
        __syncthreads();
    }

    const float inv0 = 1.f / l0;
    const float inv1 = 1.f / l1;
    __half* ob = O + ((size_t)b * S_ + q0 + wrow) * D_ + h * DK_;
    #pragma unroll
    for (int nt = 0; nt < 8; nt++) {
        *(__half2*)(ob + (size_t)fr * D_ + nt * 8 + 2 * fc) =
            __floats2half2_rn(oacc[nt][0] * inv0, oacc[nt][1] * inv0);
        *(__half2*)(ob + (size_t)(fr + 8) * D_ + nt * 8 + 2 * fc) =
            __floats2half2_rn(oacc[nt][2] * inv1, oacc[nt][3] * inv1);
    }
    #undef ISSUE_TILE
}

// ---------------------------------------------------------------------------
extern "C" void kernel_launch(void* const* d_in, const int* in_sizes, int n_in,
                              void* d_out, int out_size)
{
    const float* q  = (const float*)d_in[0];
    const float* k  = (const float*)d_in[1];
    const float* v  = (const float*)d_in[2];
    const float* wq = (const float*)d_in[3];
    const float* bq = (const float*)d_in[4];
    const float* wk = (const float*)d_in[5];
    const float* bk = (const float*)d_in[6];
    const float* wv = (const float*)d_in[7];
    const float* bv = (const float*)d_in[8];
    const float* wo = (const float*)d_in[9];
    const float* bo = (const float*)d_in[10];
    float* out = (float*)d_out;

    __half *Qs, *Ks, *Vs, *As, *Wc;
    cudaGetSymbolAddress((void**)&Qs, g_Qh);
    cudaGetSymbolAddress((void**)&Ks, g_Kh);
    cudaGetSymbolAddress((void**)&Vs, g_Vh);
    cudaGetSymbolAddress((void**)&As, g_Ah);
    cudaGetSymbolAddress((void**)&Wc, g_Wh);
    __half* WoH = Wc + 3 * (size_t)D_ * D_;

    WPtrs wp;
    wp.in[0] = wq; wp.in[1] = wk; wp.in[2] = wv; wp.in[3] = wo;
    wp.out[0] = Wc + 0 * (size_t)D_ * D_;
    wp.out[1] = Wc + 1 * (size_t)D_ * D_;
    wp.out[2] = Wc + 2 * (size_t)D_ * D_;
    wp.out[3] = WoH;

    // 1M elems per matrix, 4 floats per thread -> 1024 blocks x 4 matrices
    convertWh4<<<dim3(1024, 1, 4), 256>>>(wp);

    gemm_qkv<<<dim3(24, M_ / 128), 256>>>(q, k, v, Wc, bq, bk, bv, Qs, Ks, Vs);

    attn_fp16<<<dim3(S_ / 128, B_ * H_), 256>>>(Qs, Ks, Vs, As);

    gemm_out<<<dim3(D_ / 128, M_ / 128), 256>>>(As, WoH, bo, out);
}